// round 1
// baseline (speedup 1.0000x reference)
#include <cuda_runtime.h>
#include <cstdint>

#define NTHREADS 256
#define NWARPS   (NTHREADS / 32)

// Per-row loss scratch (device global: allocation-free, graph-safe).
__device__ float g_L[4096];
__device__ int   g_is64;

__device__ __forceinline__ float ex2f_(float a) {
    float r;
    asm("ex2.approx.ftz.f32 %0, %1;" : "=f"(r) : "f"(a));
    return r;
}
__device__ __forceinline__ float lg_(float a) {  // natural log, fast
    float r;
    asm("lg2.approx.ftz.f32 %0, %1;" : "=f"(r) : "f"(a));
    return r * 0.6931471805599453f;
}

// Detect whether targets buffer is int64 or int32.
// int64 (LE) view as int32: odd words are the (zero) high halves.
__global__ void aed_detect_kernel(const int* __restrict__ t, int B) {
    if (threadIdx.x == 0 && blockIdx.x == 0) {
        int is64 = 1;
        int n = B < 128 ? B : 128;
        for (int i = 0; i < n; i++) {
            if (t[2 * i + 1] != 0) { is64 = 0; break; }
        }
        g_is64 = is64;
    }
}

// Combine two online-softmax states sharing max M:
// z1 = sum exp(x - M), zs = sum exp((x - M)/3)
__device__ __forceinline__ void combine_soft(float& M, float& z1, float& zs,
                                             float Mo, float z1o, float zso) {
    const float K = 0.48089834696298783f;  // log2(e)/3
    float Mn = fmaxf(M, Mo);
    float ea = ex2f_((M  - Mn) * K);
    float eb = ex2f_((Mo - Mn) * K);
    z1 = z1 * (ea * ea * ea) + z1o * (eb * eb * eb);
    zs = zs * ea + zso * eb;
    M = Mn;
}
// Teacher state: zt = sum exp((t - M)/3), wt = sum exp((t - M)/3)*(m - x)
__device__ __forceinline__ void combine_teach(float& M, float& z, float& w,
                                              float Mo, float zo, float wo) {
    const float K = 0.48089834696298783f;
    float Mn = fmaxf(M, Mo);
    float ea = ex2f_((M  - Mn) * K);
    float eb = ex2f_((Mo - Mn) * K);
    z = z * ea + zo * eb;
    w = w * ea + wo * eb;
    M = Mn;
}

__global__ __launch_bounds__(NTHREADS)
void aed_row_kernel(const float* __restrict__ o0, const float* __restrict__ o1,
                    const float* __restrict__ o2, const float* __restrict__ o3,
                    const void* __restrict__ targets,
                    float* __restrict__ out, int C)
{
    const int b   = blockIdx.x;
    const int tid = threadIdx.x;
    const float K = 0.48089834696298783f;  // log2(e)/3
    const float NEG = -3.402823466e38f;

    const float4* p0 = (const float4*)(o0 + (size_t)b * C);
    const float4* p1 = (const float4*)(o1 + (size_t)b * C);
    const float4* p2 = (const float4*)(o2 + (size_t)b * C);
    const float4* p3 = (const float4*)(o3 + (size_t)b * C);
    float* mout = out + 1 + (size_t)b * C;  // mimic row (scalar loss lives at out[0])

    const int tgti = g_is64 ? (int)(((const long long*)targets)[b])
                            : ((const int*)targets)[b];

    float Mx[4], z1[4], zs[4], Mt[4], zt[4], wt[4], dots[10];
#pragma unroll
    for (int j = 0; j < 4; j++) {
        Mx[j] = NEG; z1[j] = 0.f; zs[j] = 0.f;
        Mt[j] = NEG; zt[j] = 0.f; wt[j] = 0.f;
    }
#pragma unroll
    for (int d = 0; d < 10; d++) dots[d] = 0.f;

    __shared__ float s_xt[4];
    __shared__ float sred[NWARPS][34];

    const int C4 = C >> 2;

#define UPD(j, xv)                                                     \
    do {                                                               \
        float x = (xv);                                                \
        float t = 0.8f * x + 0.2f * m;                                 \
        float Mo = Mx[j];                                              \
        float Mn = fmaxf(Mo, x);                                       \
        float e  = ex2f_((fminf(Mo, x) - Mn) * K);                     \
        float e3 = e * e * e;                                          \
        bool  gt = x > Mo;                                             \
        float u  = gt ? 1.f : e;   float r  = gt ? e  : 1.f;           \
        float u3 = gt ? 1.f : e3;  float r3 = gt ? e3 : 1.f;           \
        z1[j] = fmaf(z1[j], r3, u3);                                   \
        zs[j] = fmaf(zs[j], r,  u );                                   \
        Mx[j] = Mn;                                                    \
        float Po = Mt[j];                                              \
        float Pn = fmaxf(Po, t);                                       \
        float et = ex2f_((fminf(Po, t) - Pn) * K);                     \
        bool  g2 = t > Po;                                             \
        float ut = g2 ? 1.f : et;  float rt = g2 ? et : 1.f;           \
        zt[j] = fmaf(zt[j], rt, ut);                                   \
        wt[j] = fmaf(wt[j], rt, ut * (m - x));                         \
        Mt[j] = Pn;                                                    \
    } while (0)

    for (int i = tid; i < C4; i += NTHREADS) {
        float4 a  = __ldcs(p0 + i);
        float4 bq = __ldcs(p1 + i);
        float4 cq = __ldcs(p2 + i);
        float4 dq = __ldcs(p3 + i);

        float x0v[4] = {a.x,  a.y,  a.z,  a.w};
        float x1v[4] = {bq.x, bq.y, bq.z, bq.w};
        float x2v[4] = {cq.x, cq.y, cq.z, cq.w};
        float x3v[4] = {dq.x, dq.y, dq.z, dq.w};
        float mv[4];

#pragma unroll
        for (int v = 0; v < 4; v++) {
            float x0 = x0v[v], x1 = x1v[v], x2 = x2v[v], x3 = x3v[v];
            float m = 0.25f * ((x0 + x1) + (x2 + x3));
            mv[v] = m;
            dots[0] = fmaf(x0, x0, dots[0]);
            dots[1] = fmaf(x0, x1, dots[1]);
            dots[2] = fmaf(x0, x2, dots[2]);
            dots[3] = fmaf(x0, x3, dots[3]);
            dots[4] = fmaf(x1, x1, dots[4]);
            dots[5] = fmaf(x1, x2, dots[5]);
            dots[6] = fmaf(x1, x3, dots[6]);
            dots[7] = fmaf(x2, x2, dots[7]);
            dots[8] = fmaf(x2, x3, dots[8]);
            dots[9] = fmaf(x3, x3, dots[9]);
            UPD(0, x0);
            UPD(1, x1);
            UPD(2, x2);
            UPD(3, x3);
        }

        int cbase = i << 2;
        __stcs(mout + cbase + 0, mv[0]);
        __stcs(mout + cbase + 1, mv[1]);
        __stcs(mout + cbase + 2, mv[2]);
        __stcs(mout + cbase + 3, mv[3]);

        unsigned dv = (unsigned)(tgti - cbase);
        if (dv < 4u) {
            s_xt[0] = (dv == 0) ? x0v[0] : (dv == 1) ? x0v[1] : (dv == 2) ? x0v[2] : x0v[3];
            s_xt[1] = (dv == 0) ? x1v[0] : (dv == 1) ? x1v[1] : (dv == 2) ? x1v[2] : x1v[3];
            s_xt[2] = (dv == 0) ? x2v[0] : (dv == 1) ? x2v[1] : (dv == 2) ? x2v[2] : x2v[3];
            s_xt[3] = (dv == 0) ? x3v[0] : (dv == 1) ? x3v[1] : (dv == 2) ? x3v[2] : x3v[3];
        }
    }
#undef UPD

    // ---- warp-level reduction ----
    const unsigned FULL = 0xffffffffu;
#pragma unroll
    for (int off = 16; off > 0; off >>= 1) {
#pragma unroll
        for (int j = 0; j < 4; j++) {
            float Mo  = __shfl_down_sync(FULL, Mx[j], off);
            float z1o = __shfl_down_sync(FULL, z1[j], off);
            float zso = __shfl_down_sync(FULL, zs[j], off);
            combine_soft(Mx[j], z1[j], zs[j], Mo, z1o, zso);
            float Po  = __shfl_down_sync(FULL, Mt[j], off);
            float zto = __shfl_down_sync(FULL, zt[j], off);
            float wto = __shfl_down_sync(FULL, wt[j], off);
            combine_teach(Mt[j], zt[j], wt[j], Po, zto, wto);
        }
#pragma unroll
        for (int d = 0; d < 10; d++)
            dots[d] += __shfl_down_sync(FULL, dots[d], off);
    }

    int lane = tid & 31, wid = tid >> 5;
    if (lane == 0) {
        float* s = sred[wid];
#pragma unroll
        for (int j = 0; j < 4; j++) {
            s[j]      = Mx[j]; s[4 + j]  = z1[j]; s[8 + j]  = zs[j];
            s[12 + j] = Mt[j]; s[16 + j] = zt[j]; s[20 + j] = wt[j];
        }
#pragma unroll
        for (int d = 0; d < 10; d++) s[24 + d] = dots[d];
    }
    __syncthreads();

    if (tid == 0) {
        // fold warps 1..7 into thread 0's registers
        for (int w = 1; w < NWARPS; w++) {
            float* s = sred[w];
#pragma unroll
            for (int j = 0; j < 4; j++) {
                combine_soft(Mx[j], z1[j], zs[j], s[j], s[4 + j], s[8 + j]);
                combine_teach(Mt[j], zt[j], wt[j], s[12 + j], s[16 + j], s[20 + j]);
            }
#pragma unroll
            for (int d = 0; d < 10; d++) dots[d] += s[24 + d];
        }

        float xt[4] = {s_xt[0], s_xt[1], s_xt[2], s_xt[3]};
        const float invC = 1.0f / (float)C;
        float CE[4], KD[4];
#pragma unroll
        for (int j = 0; j < 4; j++) {
            float lse1 = Mx[j] + lg_(z1[j]);                     // logsumexp(x)
            float lses = Mx[j] * (1.f / 3.f) + lg_(zs[j]);       // logsumexp(x/T)
            float lset = Mt[j] * (1.f / 3.f) + lg_(zt[j]);       // logsumexp(t/T)
            CE[j] = lse1 - xt[j];
            float S = wt[j] / zt[j];                             // sum_c p_t*(m - x)
            KD[j] = 9.0f * invC * ((0.2f / 3.f) * S + lses - lset);
        }

        // DAL: delete target entry == subtract xt_j*xt_k from dot accumulators
        float dd[10];
        int idx = 0;
#pragma unroll
        for (int j = 0; j < 4; j++)
#pragma unroll
            for (int k = j; k < 4; k++) {
                dd[idx] = dots[idx] - xt[j] * xt[k];
                idx++;
            }
        float n0 = sqrtf(dd[0]), n1 = sqrtf(dd[4]), n2 = sqrtf(dd[7]), n3 = sqrtf(dd[9]);
        float dal = dd[1] / (n0 * n1) + dd[2] / (n0 * n2) + dd[3] / (n0 * n3)
                  + dd[5] / (n1 * n2) + dd[6] / (n1 * n3) + dd[8] / (n2 * n3);

        float irm = 0.f, mn = 3.402823466e38f;
#pragma unroll
        for (int j = 0; j < 4; j++) {
            irm += CE[j] + KD[j];
            mn = fminf(mn, CE[j]);
        }
        g_L[b] = irm + 0.7f * mn + 0.3f * dal;
    }
}

__global__ void aed_final_kernel(float* __restrict__ out, int B) {
    __shared__ float s[NTHREADS];
    float a = 0.f;
    for (int i = threadIdx.x; i < B; i += NTHREADS) a += g_L[i];
    s[threadIdx.x] = a;
    __syncthreads();
    for (int st = NTHREADS / 2; st > 0; st >>= 1) {
        if (threadIdx.x < st) s[threadIdx.x] += s[threadIdx.x + st];
        __syncthreads();
    }
    if (threadIdx.x == 0) out[0] = s[0] / (float)B;
}

extern "C" void kernel_launch(void* const* d_in, const int* in_sizes, int n_in,
                              void* d_out, int out_size) {
    const float* o0 = (const float*)d_in[0];
    const float* o1 = (const float*)d_in[1];
    const float* o2 = (const float*)d_in[2];
    const float* o3 = (const float*)d_in[3];
    const void*  tg = d_in[4];
    const int B = in_sizes[4];
    const int C = in_sizes[0] / B;
    float* out = (float*)d_out;

    aed_detect_kernel<<<1, 32>>>((const int*)tg, B);
    aed_row_kernel<<<B, NTHREADS>>>(o0, o1, o2, o3, tg, out, C);
    aed_final_kernel<<<1, NTHREADS>>>(out, B);
}